// round 3
// baseline (speedup 1.0000x reference)
#include <cuda_runtime.h>
#include <cuda_bf16.h>

// CRF score: -( sum_i logits[i, tags[i]] + sum_{i>0} transitions[tags[i-1], tags[i]] )
// logits: [S, 50] f32, tags: [S] int (dtype auto-detected int32 vs int64),
// transitions: [50, 50] f32. Output: scalar f32.
//
// Memory-bound gather: ~64MB logits sectors + 8-16MB tags. Deterministic two-pass
// reduction (block partials -> single-block final), no atomics.

#define NUM_TAGS 50
#define NBLOCKS  1184   // 148 SMs * 8

__device__ double g_part[NBLOCKS];
__device__ int    g_is64;

// Probe tags dtype: interpret first 64 entries as int64; genuine int64 tags are
// all in [0, NUM_TAGS). int32 data read as int64 packs two random tags per word
// -> value >= 2^32 almost surely. P(false 64-bit verdict) ~ (1/50)^64.
__global__ void k_detect(const long long* __restrict__ tags, int S) {
    int n = S < 64 ? S : 64;          // 512 bytes max; buffer is >= 4*S bytes
    int ok = 1;
    for (int i = 0; i < n; i++) {
        long long v = tags[i];
        if (v < 0 || v >= NUM_TAGS) { ok = 0; break; }
    }
    g_is64 = ok;
}

__global__ void __launch_bounds__(256) k_main(
    const float* __restrict__ logits,
    const void*  __restrict__ tags_raw,
    const float* __restrict__ transitions,
    int S)
{
    __shared__ float s_trans[NUM_TAGS * NUM_TAGS];
    for (int i = threadIdx.x; i < NUM_TAGS * NUM_TAGS; i += blockDim.x)
        s_trans[i] = transitions[i];
    __syncthreads();

    const int tid    = blockIdx.x * blockDim.x + threadIdx.x;
    const int stride = gridDim.x * blockDim.x;
    const int is64   = g_is64;      // uniform across grid

    float acc = 0.0f;

    if (is64) {
        const long long* __restrict__ tags = (const long long*)tags_raw;
        for (int i = tid; i < S; i += stride) {
            int t = (int)tags[i];
            acc += logits[(long long)i * NUM_TAGS + t];
            if (i + 1 < S) {
                int tn = (int)tags[i + 1];
                acc += s_trans[t * NUM_TAGS + tn];
            }
        }
    } else {
        const int* __restrict__ tags = (const int*)tags_raw;
        for (int i = tid; i < S; i += stride) {
            int t = tags[i];
            acc += logits[(long long)i * NUM_TAGS + t];
            if (i + 1 < S) {
                int tn = tags[i + 1];
                acc += s_trans[t * NUM_TAGS + tn];
            }
        }
    }

    // warp reduce
    #pragma unroll
    for (int off = 16; off > 0; off >>= 1)
        acc += __shfl_down_sync(0xFFFFFFFFu, acc, off);

    // block reduce
    __shared__ float s_warp[8];
    int lane = threadIdx.x & 31;
    int wid  = threadIdx.x >> 5;
    if (lane == 0) s_warp[wid] = acc;
    __syncthreads();
    if (wid == 0) {
        acc = (lane < (blockDim.x >> 5)) ? s_warp[lane] : 0.0f;
        #pragma unroll
        for (int off = 4; off > 0; off >>= 1)
            acc += __shfl_down_sync(0xFFFFFFFFu, acc, off);
        if (lane == 0)
            g_part[blockIdx.x] = (double)acc;   // plain store, written every launch
    }
}

__global__ void __launch_bounds__(1024) k_fin(float* __restrict__ out) {
    __shared__ double s_red[32];
    double acc = 0.0;
    for (int i = threadIdx.x; i < NBLOCKS; i += blockDim.x)
        acc += g_part[i];

    #pragma unroll
    for (int off = 16; off > 0; off >>= 1)
        acc += __shfl_down_sync(0xFFFFFFFFu, acc, off);

    int lane = threadIdx.x & 31;
    int wid  = threadIdx.x >> 5;
    if (lane == 0) s_red[wid] = acc;
    __syncthreads();
    if (wid == 0) {
        acc = (lane < 32) ? s_red[lane] : 0.0;
        #pragma unroll
        for (int off = 16; off > 0; off >>= 1)
            acc += __shfl_down_sync(0xFFFFFFFFu, acc, off);
        if (lane == 0)
            out[0] = (float)(-acc);
    }
}

extern "C" void kernel_launch(void* const* d_in, const int* in_sizes, int n_in,
                              void* d_out, int out_size) {
    const float* logits      = (const float*)d_in[0];
    const void*  tags        = d_in[1];
    const float* transitions = (const float*)d_in[2];
    float*       out         = (float*)d_out;

    const int S = in_sizes[1];  // tags element count = SEQ_LEN

    k_detect<<<1, 1>>>((const long long*)tags, S);
    k_main<<<NBLOCKS, 256>>>(logits, tags, transitions, S);
    k_fin<<<1, 1024>>>(out);
}